// round 2
// baseline (speedup 1.0000x reference)
#include <cuda_runtime.h>

#define NT   262144
#define KC   512
#define DD   64
#define TPB  512
#define SMEM_BYTES ((KC * DD + KC) * 4)

__device__ double g_loss_acc;

__global__ void vq_zero() { g_loss_acc = 0.0; }

__global__ void __launch_bounds__(TPB) vq_main(const float* __restrict__ z,
                                               const float* __restrict__ cb,
                                               float* __restrict__ out) {
    extern __shared__ float sm[];
    float* s_cb = sm;             // [KC*DD] codebook
    float* s_c2 = sm + KC * DD;   // [KC] per-code squared norms
    __shared__ double s_red[TPB / 32];

    // Cooperative codebook load (coalesced float4)
    for (int i = threadIdx.x; i < KC * DD / 4; i += TPB)
        ((float4*)s_cb)[i] = ((const float4*)cb)[i];
    __syncthreads();

    // Per-code squared norms (sequential fp32 FMA; exact order non-critical:
    // c2 error ~1e-11 << 7.6e-6 rounding grid of S+c2)
    for (int k = threadIdx.x; k < KC; k += TPB) {
        const float* row = s_cb + k * DD;
        float s = 0.0f;
#pragma unroll
        for (int d = 0; d < DD; ++d) s = __fmaf_rn(row[d], row[d], s);
        s_c2[k] = s;
    }
    __syncthreads();

    const int token = blockIdx.x * TPB + threadIdx.x;

    // z row -> registers
    float zr[DD];
    {
        const float4* zp = (const float4*)(z + (size_t)token * DD);
#pragma unroll
        for (int i = 0; i < DD / 4; ++i) {
            float4 v = zp[i];
            zr[4 * i + 0] = v.x; zr[4 * i + 1] = v.y;
            zr[4 * i + 2] = v.z; zr[4 * i + 3] = v.w;
        }
    }

    // S = sum(z^2): ulp-level error here shifts all fl(S + c2_k) identically,
    // so argmin + tie-breaks are invariant to its accumulation order.
    float S = 0.0f;
#pragma unroll
    for (int d = 0; d < DD; ++d) S = __fmaf_rn(zr[d], zr[d], S);

    float best = 3.402823466e38f;
    int   bestk = 0;

    // Score all 512 codes. Replicate reference rounding:
    //   d_k = fl( fl(S + c2_k) - fl(2 * dot_k) )   (2*dot exact)
    // Strict < with ascending k == jnp.argmin first-index tie-break.
#pragma unroll 1
    for (int k = 0; k < KC; k += 4) {
        float dot0 = 0.0f, dot1 = 0.0f, dot2 = 0.0f, dot3 = 0.0f;
        const float4* r0 = (const float4*)(s_cb + (k + 0) * DD);
        const float4* r1 = (const float4*)(s_cb + (k + 1) * DD);
        const float4* r2 = (const float4*)(s_cb + (k + 2) * DD);
        const float4* r3 = (const float4*)(s_cb + (k + 3) * DD);
#pragma unroll
        for (int i = 0; i < DD / 4; ++i) {
            float4 a = r0[i], b = r1[i], c = r2[i], e = r3[i];
            float z0 = zr[4 * i + 0], z1 = zr[4 * i + 1];
            float z2 = zr[4 * i + 2], z3 = zr[4 * i + 3];
            dot0 = __fmaf_rn(a.x, z0, dot0); dot0 = __fmaf_rn(a.y, z1, dot0);
            dot0 = __fmaf_rn(a.z, z2, dot0); dot0 = __fmaf_rn(a.w, z3, dot0);
            dot1 = __fmaf_rn(b.x, z0, dot1); dot1 = __fmaf_rn(b.y, z1, dot1);
            dot1 = __fmaf_rn(b.z, z2, dot1); dot1 = __fmaf_rn(b.w, z3, dot1);
            dot2 = __fmaf_rn(c.x, z0, dot2); dot2 = __fmaf_rn(c.y, z1, dot2);
            dot2 = __fmaf_rn(c.z, z2, dot2); dot2 = __fmaf_rn(c.w, z3, dot2);
            dot3 = __fmaf_rn(e.x, z0, dot3); dot3 = __fmaf_rn(e.y, z1, dot3);
            dot3 = __fmaf_rn(e.z, z2, dot3); dot3 = __fmaf_rn(e.w, z3, dot3);
        }
        float s0 = __fsub_rn(__fadd_rn(S, s_c2[k + 0]), __fmul_rn(2.0f, dot0));
        float s1 = __fsub_rn(__fadd_rn(S, s_c2[k + 1]), __fmul_rn(2.0f, dot1));
        float s2 = __fsub_rn(__fadd_rn(S, s_c2[k + 2]), __fmul_rn(2.0f, dot2));
        float s3 = __fsub_rn(__fadd_rn(S, s_c2[k + 3]), __fmul_rn(2.0f, dot3));
        if (s0 < best) { best = s0; bestk = k + 0; }
        if (s1 < best) { best = s1; bestk = k + 1; }
        if (s2 < best) { best = s2; bestk = k + 2; }
        if (s3 < best) { best = s3; bestk = k + 3; }
    }

    // Epilogue: z_q_st = fl(z + fl(z_q - z)) (bitwise-replicates reference),
    // loss partial = sum fl(z_q - z)^2
    const float4* q = (const float4*)(s_cb + bestk * DD);
    float4* op = (float4*)(out + (size_t)token * DD);
    float lacc = 0.0f;
#pragma unroll
    for (int i = 0; i < DD / 4; ++i) {
        float4 c = q[i];
        float z0 = zr[4 * i + 0], z1 = zr[4 * i + 1];
        float z2 = zr[4 * i + 2], z3 = zr[4 * i + 3];
        float4 o;
        float dx;
        dx = __fsub_rn(c.x, z0); o.x = __fadd_rn(z0, dx); lacc = __fmaf_rn(dx, dx, lacc);
        dx = __fsub_rn(c.y, z1); o.y = __fadd_rn(z1, dx); lacc = __fmaf_rn(dx, dx, lacc);
        dx = __fsub_rn(c.z, z2); o.z = __fadd_rn(z2, dx); lacc = __fmaf_rn(dx, dx, lacc);
        dx = __fsub_rn(c.w, z3); o.w = __fadd_rn(z3, dx); lacc = __fmaf_rn(dx, dx, lacc);
        op[i] = o;
    }

    // Block reduction of loss in double, then one atomicAdd per block
    double da = (double)lacc;
#pragma unroll
    for (int o = 16; o > 0; o >>= 1)
        da += __shfl_down_sync(0xFFFFFFFFu, da, o);
    const int lane = threadIdx.x & 31;
    const int warp = threadIdx.x >> 5;
    if (lane == 0) s_red[warp] = da;
    __syncthreads();
    if (threadIdx.x == 0) {
        double t = 0.0;
#pragma unroll
        for (int w = 0; w < TPB / 32; ++w) t += s_red[w];
        atomicAdd(&g_loss_acc, t);
    }
}

__global__ void vq_fin(float* __restrict__ out, int loss_idx) {
    double m = g_loss_acc / (double)((long long)NT * DD);
    float m32 = (float)m;
    // reference: loss = fl(q + fl(0.25 * e)), q == e == m32
    out[loss_idx] = __fadd_rn(m32, __fmul_rn(0.25f, m32));
}

extern "C" void kernel_launch(void* const* d_in, const int* in_sizes, int n_in,
                              void* d_out, int out_size) {
    const float* z;
    const float* cb;
    if (in_sizes[0] == NT * DD) {
        z = (const float*)d_in[0];
        cb = (const float*)d_in[1];
    } else {
        z = (const float*)d_in[1];
        cb = (const float*)d_in[0];
    }
    float* out = (float*)d_out;

    cudaFuncSetAttribute(vq_main, cudaFuncAttributeMaxDynamicSharedMemorySize,
                         SMEM_BYTES);

    vq_zero<<<1, 1>>>();
    vq_main<<<NT / TPB, TPB, SMEM_BYTES>>>(z, cb, out);
    vq_fin<<<1, 1>>>(out, out_size - 1);
}

// round 4
// speedup vs baseline: 1.0337x; 1.0337x over previous
#include <cuda_runtime.h>

#define NT   262144
#define KC   512
#define DD   64
#define TPB  512
#define SMEM_BYTES ((KC * DD + KC) * 4)

typedef unsigned long long u64;

__device__ double g_loss_acc;

__global__ void vq_zero() { g_loss_acc = 0.0; }

// Packed 2-wide fp32 FMA (Blackwell FFMA2): d = a*b + c elementwise on (lo,hi)
__device__ __forceinline__ u64 ffma2(u64 a, u64 b, u64 c) {
    u64 d;
    asm("fma.rn.f32x2 %0, %1, %2, %3;" : "=l"(d) : "l"(a), "l"(b), "l"(c));
    return d;
}

__device__ __forceinline__ float2 unpack2(u64 v) {
    float2 r;
    asm("mov.b64 {%0, %1}, %2;" : "=f"(r.x), "=f"(r.y) : "l"(v));
    return r;
}

// Branchless top-3 (ascending) insert
#define INSERT3(s, kk)                                                        \
    do {                                                                      \
        bool lt0 = (s) < v0, lt1 = (s) < v1, lt2 = (s) < v2;                  \
        float nv2 = lt2 ? (lt1 ? v1 : (s)) : v2;                              \
        int   ni2 = lt2 ? (lt1 ? i1 : (kk)) : i2;                             \
        float nv1 = lt1 ? (lt0 ? v0 : (s)) : v1;                              \
        int   ni1 = lt1 ? (lt0 ? i0 : (kk)) : i1;                             \
        float nv0 = lt0 ? (s) : v0;                                           \
        int   ni0 = lt0 ? (kk) : i0;                                          \
        v0 = nv0; v1 = nv1; v2 = nv2; i0 = ni0; i1 = ni1; i2 = ni2;           \
    } while (0)

__global__ void __launch_bounds__(TPB) vq_main(const float* __restrict__ z,
                                               const float* __restrict__ cb,
                                               float* __restrict__ out) {
    extern __shared__ float sm[];
    float* s_cb = sm;             // [KC*DD] codebook (fp32, exact)
    float* s_c2 = sm + KC * DD;   // [KC] per-code squared norms
    __shared__ double s_red[TPB / 32];

    // Cooperative codebook load (coalesced float4)
    for (int i = threadIdx.x; i < KC * DD / 4; i += TPB)
        ((float4*)s_cb)[i] = ((const float4*)cb)[i];
    __syncthreads();

    // Per-code squared norms, sequential fp32 FMA (order matches R2-passing kernel)
    for (int k = threadIdx.x; k < KC; k += TPB) {
        const float* row = s_cb + k * DD;
        float s = 0.0f;
#pragma unroll
        for (int d = 0; d < DD; ++d) s = __fmaf_rn(row[d], row[d], s);
        s_c2[k] = s;
    }
    __syncthreads();

    const int token = blockIdx.x * TPB + threadIdx.x;

    // z row -> packed f32x2 registers
    u64 zq[DD / 2];
    {
        const ulonglong2* zp = (const ulonglong2*)(z + (size_t)token * DD);
#pragma unroll
        for (int i = 0; i < DD / 4; ++i) {
            ulonglong2 v = zp[i];
            zq[2 * i + 0] = v.x;
            zq[2 * i + 1] = v.y;
        }
    }

    // ---- Filter: approx score  fl(c2_k - fl(2*dot_k))  via packed FFMA2.
    // Identical expression to the exact score minus the common S add, so the
    // only filter-vs-exact deviation is packed accumulation order (~1e-7),
    // << typical 1st-2nd gap ~6e-3. Top-3 covers quantized tie buckets
    // (width ulp(64)=7.6e-6) up to 3 members.
    const float FINF = __int_as_float(0x7f800000);
    float v0 = FINF, v1 = FINF, v2 = FINF;
    int   i0 = 0,    i1 = 0,    i2 = 0;

#pragma unroll 1
    for (int k = 0; k < KC; k += 4) {
        u64 a0 = 0ull, a1 = 0ull, a2 = 0ull, a3 = 0ull;
        const ulonglong2* r0 = (const ulonglong2*)(s_cb + (k + 0) * DD);
        const ulonglong2* r1 = (const ulonglong2*)(s_cb + (k + 1) * DD);
        const ulonglong2* r2 = (const ulonglong2*)(s_cb + (k + 2) * DD);
        const ulonglong2* r3 = (const ulonglong2*)(s_cb + (k + 3) * DD);
#pragma unroll
        for (int i = 0; i < DD / 4; ++i) {
            ulonglong2 ca = r0[i], cbv = r1[i], cc = r2[i], cd = r3[i];
            u64 zlo = zq[2 * i + 0], zhi = zq[2 * i + 1];
            a0 = ffma2(ca.x,  zlo, a0); a0 = ffma2(ca.y,  zhi, a0);
            a1 = ffma2(cbv.x, zlo, a1); a1 = ffma2(cbv.y, zhi, a1);
            a2 = ffma2(cc.x,  zlo, a2); a2 = ffma2(cc.y,  zhi, a2);
            a3 = ffma2(cd.x,  zlo, a3); a3 = ffma2(cd.y,  zhi, a3);
        }
        float2 p0 = unpack2(a0), p1 = unpack2(a1), p2 = unpack2(a2), p3 = unpack2(a3);
        float s0 = __fsub_rn(s_c2[k + 0], __fmul_rn(2.0f, __fadd_rn(p0.x, p0.y)));
        float s1 = __fsub_rn(s_c2[k + 1], __fmul_rn(2.0f, __fadd_rn(p1.x, p1.y)));
        float s2 = __fsub_rn(s_c2[k + 2], __fmul_rn(2.0f, __fadd_rn(p2.x, p2.y)));
        float s3 = __fsub_rn(s_c2[k + 3], __fmul_rn(2.0f, __fadd_rn(p3.x, p3.y)));
        INSERT3(s0, k + 0);
        INSERT3(s1, k + 1);
        INSERT3(s2, k + 2);
        INSERT3(s3, k + 3);
    }

    // ---- Exact rescore of the 3 candidates (replicates reference rounding:
    //      fl( fl(S + c2_k) - fl(2 * dot_k) ), sequential fp32 FMA dot).
    float S = 0.0f;
#pragma unroll
    for (int i = 0; i < DD / 2; ++i) {
        float2 p = unpack2(zq[i]);
        S = __fmaf_rn(p.x, p.x, S);
        S = __fmaf_rn(p.y, p.y, S);
    }

    float e0, e1, e2;
    {
        const float* ra = s_cb + i0 * DD;
        const float* rb = s_cb + i1 * DD;
        const float* rc = s_cb + i2 * DD;
        float da = 0.0f, db = 0.0f, dc = 0.0f;
#pragma unroll
        for (int i = 0; i < DD / 2; ++i) {
            float2 p = unpack2(zq[i]);
            da = __fmaf_rn(ra[2 * i], p.x, da); da = __fmaf_rn(ra[2 * i + 1], p.y, da);
            db = __fmaf_rn(rb[2 * i], p.x, db); db = __fmaf_rn(rb[2 * i + 1], p.y, db);
            dc = __fmaf_rn(rc[2 * i], p.x, dc); dc = __fmaf_rn(rc[2 * i + 1], p.y, dc);
        }
        e0 = __fsub_rn(__fadd_rn(S, s_c2[i0]), __fmul_rn(2.0f, da));
        e1 = __fsub_rn(__fadd_rn(S, s_c2[i1]), __fmul_rn(2.0f, db));
        e2 = __fsub_rn(__fadd_rn(S, s_c2[i2]), __fmul_rn(2.0f, dc));
    }

    // argmin with first-index tie-break (jnp.argmin semantics)
    int   bestk = i0;
    float bests = e0;
    if (e1 < bests || (e1 == bests && i1 < bestk)) { bests = e1; bestk = i1; }
    if (e2 < bests || (e2 == bests && i2 < bestk)) { bests = e2; bestk = i2; }

    // ---- Epilogue: z_q_st = fl(z + fl(z_q - z)); loss partial = sum fl(z_q-z)^2
    const float4* q = (const float4*)(s_cb + bestk * DD);
    float4* op = (float4*)(out + (size_t)token * DD);
    float lacc = 0.0f;
#pragma unroll
    for (int i = 0; i < DD / 4; ++i) {
        float4 c = q[i];
        float2 plo = unpack2(zq[2 * i + 0]);
        float2 phi = unpack2(zq[2 * i + 1]);
        float4 o;
        float dx;
        dx = __fsub_rn(c.x, plo.x); o.x = __fadd_rn(plo.x, dx); lacc = __fmaf_rn(dx, dx, lacc);
        dx = __fsub_rn(c.y, plo.y); o.y = __fadd_rn(plo.y, dx); lacc = __fmaf_rn(dx, dx, lacc);
        dx = __fsub_rn(c.z, phi.x); o.z = __fadd_rn(phi.x, dx); lacc = __fmaf_rn(dx, dx, lacc);
        dx = __fsub_rn(c.w, phi.y); o.w = __fadd_rn(phi.y, dx); lacc = __fmaf_rn(dx, dx, lacc);
        op[i] = o;
    }

    // Block reduction of loss in double, then one atomicAdd per block
    double da = (double)lacc;
#pragma unroll
    for (int o = 16; o > 0; o >>= 1)
        da += __shfl_down_sync(0xFFFFFFFFu, da, o);
    const int lane = threadIdx.x & 31;
    const int warp = threadIdx.x >> 5;
    if (lane == 0) s_red[warp] = da;
    __syncthreads();
    if (threadIdx.x == 0) {
        double t = 0.0;
#pragma unroll
        for (int w = 0; w < TPB / 32; ++w) t += s_red[w];
        atomicAdd(&g_loss_acc, t);
    }
}

__global__ void vq_fin(float* __restrict__ out, int loss_idx) {
    double m = g_loss_acc / (double)((long long)NT * DD);
    float m32 = (float)m;
    // reference: loss = fl(q + fl(0.25 * e)), q == e == m32
    out[loss_idx] = __fadd_rn(m32, __fmul_rn(0.25f, m32));
}

extern "C" void kernel_launch(void* const* d_in, const int* in_sizes, int n_in,
                              void* d_out, int out_size) {
    const float* z;
    const float* cb;
    if (in_sizes[0] == NT * DD) {
        z = (const float*)d_in[0];
        cb = (const float*)d_in[1];
    } else {
        z = (const float*)d_in[1];
        cb = (const float*)d_in[0];
    }
    float* out = (float*)d_out;

    cudaFuncSetAttribute(vq_main, cudaFuncAttributeMaxDynamicSharedMemorySize,
                         SMEM_BYTES);

    vq_zero<<<1, 1>>>();
    vq_main<<<NT / TPB, TPB, SMEM_BYTES>>>(z, cb, out);
    vq_fin<<<1, 1>>>(out, out_size - 1);
}